// round 1
// baseline (speedup 1.0000x reference)
#include <cuda_runtime.h>
#include <cuda_bf16.h>
#include <cmath>

// Problem constants
#define BATCH 32
#define NPTS  1024
#define FDIM  7
#define HID   256
#define MLP_H 64
#define OUTD  8
#define NCHUNK 4           // row chunks per batch for the pairwise kernels
#define CHUNK (NPTS/NCHUNK)

// ---------------- scratch (device globals; no allocation APIs) ----------------
__device__ float    g_dinv[BATCH*NPTS];
__device__ unsigned g_adjw[BATCH*NPTS*32];      // adjacency bitmask, 32 words/row (4 MB)
__device__ float    g_pp0[BATCH*NPTS];          // (nadj@pts)[:,0]
__device__ float    g_pp1[BATCH*NPTS];          // (nadj@pts)[:,1]
__device__ float    g_cc [BATCH*NPTS];          // column weights c_j
__device__ float    g_maxpart[BATCH*NCHUNK];
__device__ float    g_spdpart[BATCH*NCHUNK];
__device__ float    g_upart[BATCH*NCHUNK*HID];  // partial sums of c_j*h_j
__device__ float    g_feat[BATCH*328];          // [0:64) mlp (unused here), [64:320) gcn, [320:328) glo
__device__ float    g_mlpPart[BATCH*7*MLP_H];

// ---------------- K1: pairwise pass 1 — degree, adjacency bitmask, max d2, speed ----------------
__global__ void __launch_bounds__(256)
k_adj(const float* __restrict__ x, float C) {
    const int b = blockIdx.y, chunk = blockIdx.x;
    const int tid = threadIdx.x;
    const int lane = tid & 31, w = tid >> 5;      // 8 warps

    __shared__ float p0[NPTS], p1[NPTS];
    __shared__ float red[256];

    for (int i = tid; i < NPTS; i += 256) {
        const float* xp = x + (size_t)(b*NPTS + i)*FDIM;
        p0[i] = xp[1];
        p1[i] = xp[2];
    }
    __syncthreads();

    float mx = 0.0f;
    const int jbase = chunk*CHUNK + w*32;
    for (int r = 0; r < 32; r++) {
        const int j = jbase + r;
        const float pj0 = p0[j], pj1 = p1[j];
        int cnt = 0;
        unsigned myword = 0;
        #pragma unroll 8
        for (int it = 0; it < 32; it++) {
            const int k = it*32 + lane;
            const float dx = p0[k] - pj0;
            const float dy = p1[k] - pj1;
            const float d2 = fmaf(dx, dx, dy*dy);
            mx = fmaxf(mx, d2);
            const unsigned bal = __ballot_sync(0xffffffffu, d2 < C);
            cnt += __popc(bal);
            if (lane == it) myword = bal;
        }
        g_adjw[(size_t)(b*NPTS + j)*32 + lane] = myword;   // coalesced 128B/row
        if (lane == 0) g_dinv[b*NPTS + j] = 1.0f / sqrtf((float)cnt);
    }

    // speed for one row per thread
    const int jr = chunk*CHUNK + tid;
    const float* xp = x + (size_t)(b*NPTS + jr)*FDIM;
    const float x3 = xp[3], x4 = xp[4];
    const float sp = sqrtf(fmaf(x3, x3, x4*x4));

    // block reductions
    red[tid] = mx; __syncthreads();
    for (int s = 128; s > 0; s >>= 1) {
        if (tid < s) red[tid] = fmaxf(red[tid], red[tid + s]);
        __syncthreads();
    }
    if (tid == 0) g_maxpart[b*NCHUNK + chunk] = red[0];
    __syncthreads();
    red[tid] = sp; __syncthreads();
    for (int s = 128; s > 0; s >>= 1) {
        if (tid < s) red[tid] = red[tid] + red[tid + s];
        __syncthreads();
    }
    if (tid == 0) g_spdpart[b*NCHUNK + chunk] = red[0];
}

// ---------------- K2: pass 2 — gather s_j, t_j from bitmask (sparse, ~2.2% set) ----------------
__global__ void __launch_bounds__(256)
k_gather(const float* __restrict__ x) {
    const int b = blockIdx.y, chunk = blockIdx.x;
    const int tid = threadIdx.x;

    __shared__ float p0[NPTS], p1[NPTS], dv[NPTS];
    for (int i = tid; i < NPTS; i += 256) {
        const float* xp = x + (size_t)(b*NPTS + i)*FDIM;
        p0[i] = xp[1];
        p1[i] = xp[2];
        dv[i] = g_dinv[b*NPTS + i];
    }
    __syncthreads();

    const int j = chunk*CHUNK + tid;
    const unsigned* aw = &g_adjw[(size_t)(b*NPTS + j)*32];
    float s0 = 0.f, s1 = 0.f, t = 0.f;
    for (int wi = 0; wi < 32; wi++) {
        unsigned m = aw[wi];
        while (m) {
            const int i = __ffs(m) - 1;
            m &= m - 1;
            const int k = wi*32 + i;
            const float d = dv[k];
            s0 = fmaf(d, p0[k], s0);
            s1 = fmaf(d, p1[k], s1);
            t += d;
        }
    }
    const float dj = dv[j];
    g_pp0[b*NPTS + j] = dj * s0;
    g_pp1[b*NPTS + j] = dj * s1;
    g_cc [b*NPTS + j] = dj * t;
}

// ---------------- K3: u partial — Σ_j c_j * relu(W1·pp_j + b1), per 256-row chunk ----------------
__global__ void __launch_bounds__(256)
k_upart(const float* __restrict__ W1, const float* __restrict__ b1) {
    const int b = blockIdx.y, chunk = blockIdx.x;
    const int d = threadIdx.x;                 // 256 hidden dims

    __shared__ float sp0[CHUNK], sp1[CHUNK], sc[CHUNK];
    const int base = b*NPTS + chunk*CHUNK;
    sp0[d] = g_pp0[base + d];
    sp1[d] = g_pp1[base + d];
    sc [d] = g_cc [base + d];
    __syncthreads();

    const float w0 = W1[2*d], w1 = W1[2*d + 1], bd = b1[d];
    float acc = 0.f;
    #pragma unroll 4
    for (int jj = 0; jj < CHUNK; jj++) {
        float a = fmaf(w1, sp1[jj], fmaf(w0, sp0[jj], bd));
        a = fmaxf(a, 0.f);
        acc = fmaf(sc[jj], a, acc);
    }
    g_upart[(b*NCHUNK + chunk)*HID + d] = acc;
}

// ---------------- K4: per-batch GCN finish (W2, Wfc) + global branch ----------------
__global__ void __launch_bounds__(256)
k_gcn(const float* __restrict__ W2, const float* __restrict__ b2,
      const float* __restrict__ Wfc, const float* __restrict__ bfc,
      const float* __restrict__ Wg, const float* __restrict__ bg) {
    const int b = blockIdx.x;
    const int d = threadIdx.x;                 // 256

    __shared__ float m[HID], z1[HID];
    __shared__ float gl[2];

    float u = g_upart[(b*NCHUNK + 0)*HID + d]
            + g_upart[(b*NCHUNK + 1)*HID + d]
            + g_upart[(b*NCHUNK + 2)*HID + d]
            + g_upart[(b*NCHUNK + 3)*HID + d];
    m[d] = u * (1.0f/1024.0f);

    if (d == 0) {
        const float mx = fmaxf(fmaxf(g_maxpart[b*NCHUNK+0], g_maxpart[b*NCHUNK+1]),
                               fmaxf(g_maxpart[b*NCHUNK+2], g_maxpart[b*NCHUNK+3]));
        gl[1] = 1.0f / sqrtf(mx);   // density = 1/max(dist) = 1/sqrt(max d2)
        gl[0] = (g_spdpart[b*NCHUNK+0] + g_spdpart[b*NCHUNK+1]
               + g_spdpart[b*NCHUNK+2] + g_spdpart[b*NCHUNK+3]) * (1.0f/1024.0f);
    }
    __syncthreads();

    // z1 = W2 @ m + b2
    {
        float acc = b2[d];
        const float4* Wr = (const float4*)(W2 + (size_t)d*HID);
        const float4* ms = (const float4*)m;
        #pragma unroll 8
        for (int e = 0; e < HID/4; e++) {
            const float4 wv = Wr[e];
            const float4 mv = ms[e];
            acc = fmaf(wv.x, mv.x, acc);
            acc = fmaf(wv.y, mv.y, acc);
            acc = fmaf(wv.z, mv.z, acc);
            acc = fmaf(wv.w, mv.w, acc);
        }
        z1[d] = acc;
    }
    __syncthreads();

    // gcn_en = Wfc @ z1 + bfc
    {
        float acc = bfc[d];
        const float4* Wr = (const float4*)(Wfc + (size_t)d*HID);
        const float4* zs = (const float4*)z1;
        #pragma unroll 8
        for (int e = 0; e < HID/4; e++) {
            const float4 wv = Wr[e];
            const float4 zv = zs[e];
            acc = fmaf(wv.x, zv.x, acc);
            acc = fmaf(wv.y, zv.y, acc);
            acc = fmaf(wv.z, zv.z, acc);
            acc = fmaf(wv.w, zv.w, acc);
        }
        g_feat[b*328 + 64 + d] = acc;
    }

    // glo_en = relu(Wg @ [avg_speed, density] + bg)
    if (d < OUTD) {
        const float ge = fmaf(Wg[2*d], gl[0], fmaf(Wg[2*d + 1], gl[1], bg[d]));
        g_feat[b*328 + 320 + d] = fmaxf(ge, 0.f);
    }
}

// ---------------- K5: MLP layer 1 partials over 1024-feature slices ----------------
__global__ void __launch_bounds__(256)
k_mlp1(const float* __restrict__ x, const float* __restrict__ Wm0) {
    const int b = blockIdx.y, sl = blockIdx.x;   // 7 slices
    const int tid = threadIdx.x;
    const int h = tid & 63, sc = tid >> 6;        // 64 outputs x 4 subchunks

    __shared__ float part[4][MLP_H];
    const int fbase = sl*1024 + sc*256;
    const float4* xv = (const float4*)(x + (size_t)b*(NPTS*FDIM) + fbase);
    const float4* wv = (const float4*)(Wm0 + (size_t)h*(NPTS*FDIM) + fbase);
    float acc = 0.f;
    #pragma unroll 4
    for (int i = 0; i < 64; i++) {
        const float4 a = xv[i];
        const float4 ww = wv[i];
        acc = fmaf(a.x, ww.x, acc);
        acc = fmaf(a.y, ww.y, acc);
        acc = fmaf(a.z, ww.z, acc);
        acc = fmaf(a.w, ww.w, acc);
    }
    part[sc][h] = acc;
    __syncthreads();
    if (tid < MLP_H)
        g_mlpPart[(b*7 + sl)*MLP_H + tid] =
            part[0][tid] + part[1][tid] + part[2][tid] + part[3][tid];
}

// ---------------- K6: MLP finish + output projection ----------------
__global__ void __launch_bounds__(64)
k_final(const float* __restrict__ Wm1, const float* __restrict__ bm1,
        const float* __restrict__ bm0,
        const float* __restrict__ Wp, const float* __restrict__ bp,
        float* __restrict__ out) {
    const int b = blockIdx.x;
    const int tid = threadIdx.x;                  // 64

    __shared__ float m0[MLP_H], m1[MLP_H];
    float a = bm0[tid];
    #pragma unroll
    for (int s = 0; s < 7; s++) a += g_mlpPart[(b*7 + s)*MLP_H + tid];
    m0[tid] = fmaxf(a, 0.f);
    __syncthreads();

    float acc = bm1[tid];
    const float* wr = Wm1 + (size_t)tid*MLP_H;
    #pragma unroll 8
    for (int e = 0; e < MLP_H; e++) acc = fmaf(wr[e], m0[e], acc);
    m1[tid] = fmaxf(acc, 0.f);
    __syncthreads();

    if (tid < OUTD) {
        float o = bp[tid];
        const float* wp = Wp + (size_t)tid*328;
        #pragma unroll 8
        for (int k = 0; k < MLP_H; k++) o = fmaf(wp[k], m1[k], o);
        const float* ft = &g_feat[b*328];
        #pragma unroll 8
        for (int k = 64; k < 328; k++) o = fmaf(wp[k], ft[k], o);
        out[b*OUTD + tid] = o;
    }
}

// ---------------- launch ----------------
extern "C" void kernel_launch(void* const* d_in, const int* in_sizes, int n_in,
                              void* d_out, int out_size) {
    (void)in_sizes; (void)n_in; (void)out_size;
    const float* x   = (const float*)d_in[0];
    const float* W1  = (const float*)d_in[1];
    const float* b1  = (const float*)d_in[2];
    const float* W2  = (const float*)d_in[3];
    const float* b2  = (const float*)d_in[4];
    const float* Wfc = (const float*)d_in[5];
    const float* bfc = (const float*)d_in[6];
    const float* Wg  = (const float*)d_in[7];
    const float* bg  = (const float*)d_in[8];
    const float* Wm0 = (const float*)d_in[9];
    const float* bm0 = (const float*)d_in[10];
    const float* Wm1 = (const float*)d_in[11];
    const float* bm1 = (const float*)d_in[12];
    const float* Wp  = (const float*)d_in[13];
    const float* bp  = (const float*)d_in[14];
    float* out = (float*)d_out;

    // Exact threshold: smallest float C with sqrtf(C) >= 0.3f, so that
    // (d2 < C)  <==>  (sqrtf(d2) < 0.3f). Cheap, deterministic host compute.
    float C = 0.09f;
    while (sqrtf(C) >= 0.3f) C = nextafterf(C, 0.0f);
    while (sqrtf(C) <  0.3f) C = nextafterf(C, 1.0f);

    dim3 gPair(NCHUNK, BATCH);
    k_adj   <<<gPair, 256>>>(x, C);
    k_gather<<<gPair, 256>>>(x);
    k_upart <<<gPair, 256>>>(W1, b1);
    k_gcn   <<<BATCH, 256>>>(W2, b2, Wfc, bfc, Wg, bg);
    k_mlp1  <<<dim3(7, BATCH), 256>>>(x, Wm0);
    k_final <<<BATCH, 64>>>(Wm1, bm1, bm0, Wp, bp, out);
}

// round 2
// speedup vs baseline: 1.5152x; 1.5152x over previous
#include <cuda_runtime.h>
#include <cuda_bf16.h>
#include <cmath>

#define BATCH 32
#define NPTS  1024
#define FDIM  7
#define HID   256
#define MLP_H 64
#define OUTD  8

// ---------------- scratch (device globals) ----------------
// adjacency words, layout: word(row k, colblock jb) at [(b*32 + jb)*1024 + k]
__device__ unsigned g_adjw[BATCH*32*NPTS];        // 4 MB
__device__ float4   g_ppc[BATCH*NPTS];            // (pp0, pp1, cc, 0)
__device__ float    g_maxpart[BATCH*8];
__device__ float    g_glo[BATCH*2];               // avg_speed, density
__device__ float    g_upart[BATCH*4*HID];
__device__ float    g_feat[BATCH*328];            // [64:320) gcn, [320:328) glo
__device__ float    g_mlpPart[BATCH*7*MLP_H];

// ---------------- K1: pairwise adjacency (column-ballot, expanded form) ----------------
// grid (8, BATCH), 256 thr. Warp w: colblock jb = grp*4 + (w&3), k-half = (w>>2).
__global__ void __launch_bounds__(256)
k_adj(const float* __restrict__ x, float C) {
    const int b = blockIdx.y, grp = blockIdx.x;
    const int tid = threadIdx.x;
    const int lane = tid & 31, w = tid >> 5;

    __shared__ float4 P[NPTS];         // (p0, p1, |p|^2, 0) — 16KB
    __shared__ float  wmax[8];

    for (int i = tid; i < NPTS; i += 256) {
        const float* xp = x + (size_t)(b*NPTS + i)*FDIM;
        const float p0 = xp[1], p1 = xp[2];
        P[i] = make_float4(p0, p1, fmaf(p0, p0, p1*p1), 0.f);
    }
    __syncthreads();

    const int jb = grp*4 + (w & 3);
    const int j  = jb*32 + lane;
    const float4 pj = P[j];
    const float m2p0 = -2.0f*pj.x, m2p1 = -2.0f*pj.y;
    const float cj = C - pj.z;
    float emax = -1e30f;

    const int k0 = (w >> 2) * 512;
    unsigned* __restrict__ outp = &g_adjw[((size_t)b*32 + jb)*NPTS];

    for (int kb = 0; kb < 16; kb++) {
        unsigned myw = 0;
        const float4* Pk = &P[k0 + kb*32];
        #pragma unroll
        for (int t = 0; t < 32; t++) {
            const float4 pk = Pk[t];                         // broadcast LDS.128
            const float e = fmaf(m2p0, pk.x, fmaf(m2p1, pk.y, pk.z));
            emax = fmaxf(emax, e);
            const unsigned bal = __ballot_sync(0xffffffffu, e < cj);
            if (lane == t) myw = bal;                        // lane t keeps row k0+kb*32+t
        }
        outp[k0 + kb*32 + lane] = myw;                       // coalesced 128B store
    }

    // max d2 partial: d2 = e + nj
    float dmax = emax + pj.z;
    #pragma unroll
    for (int s = 16; s > 0; s >>= 1)
        dmax = fmaxf(dmax, __shfl_xor_sync(0xffffffffu, dmax, s));
    if (lane == 0) wmax[w] = dmax;
    __syncthreads();
    if (tid == 0) {
        float mx = wmax[0];
        #pragma unroll
        for (int i = 1; i < 8; i++) mx = fmaxf(mx, wmax[i]);
        g_maxpart[b*8 + grp] = mx;
    }
}

// ---------------- K2: degrees + sparse gather + global branch scalars ----------------
// grid (BATCH), 1024 thr — one thread per row.
__global__ void __launch_bounds__(1024)
k_gup(const float* __restrict__ x) {
    const int b = blockIdx.x;
    const int j = threadIdx.x;
    const int lane = j & 31, wid = j >> 5;

    __shared__ float sp0[NPTS], sp1[NPTS], sdv[NPTS];
    __shared__ float red[32];

    const float* xp = x + (size_t)(b*NPTS + j)*FDIM;
    const float p0 = xp[1], p1 = xp[2];
    const float x3 = xp[3], x4 = xp[4];
    sp0[j] = p0; sp1[j] = p1;
    float sp = sqrtf(fmaf(x3, x3, x4*x4));

    // row j's adjacency words + degree
    unsigned wr[32]; int cnt = 0;
    #pragma unroll
    for (int cb = 0; cb < 32; cb++) {
        wr[cb] = g_adjw[((size_t)b*32 + cb)*NPTS + j];       // coalesced per cb
        cnt += __popc(wr[cb]);
    }
    const float dinv = 1.0f / sqrtf((float)cnt);
    sdv[j] = dinv;

    // speed partial reduce
    #pragma unroll
    for (int s = 16; s > 0; s >>= 1) sp += __shfl_xor_sync(0xffffffffu, sp, s);
    if (lane == 0) red[wid] = sp;
    __syncthreads();

    // sparse gather
    float s0 = 0.f, s1 = 0.f, t = 0.f;
    for (int cb = 0; cb < 32; cb++) {
        unsigned m = wr[cb];
        const int base = cb*32;
        while (m) {
            const int i = __ffs(m) - 1;
            m &= m - 1;
            const int k = base + i;
            const float d = sdv[k];
            s0 = fmaf(d, sp0[k], s0);
            s1 = fmaf(d, sp1[k], s1);
            t += d;
        }
    }
    g_ppc[b*NPTS + j] = make_float4(dinv*s0, dinv*s1, dinv*t, 0.f);

    if (wid == 0) {
        float v = red[lane];
        #pragma unroll
        for (int s = 16; s > 0; s >>= 1) v += __shfl_xor_sync(0xffffffffu, v, s);
        if (lane == 0) {
            float mx = g_maxpart[b*8];
            #pragma unroll
            for (int i = 1; i < 8; i++) mx = fmaxf(mx, g_maxpart[b*8 + i]);
            g_glo[b*2 + 0] = v * (1.0f/1024.0f);
            g_glo[b*2 + 1] = 1.0f / sqrtf(mx);
        }
    }
}

// ---------------- K3: u partials — sum_j c_j * relu(W1·pp_j + b1) ----------------
__global__ void __launch_bounds__(256)
k_upart(const float* __restrict__ W1, const float* __restrict__ b1) {
    const int chunk = blockIdx.x, b = blockIdx.y;
    const int d = threadIdx.x;

    __shared__ float4 S[256];
    S[d] = g_ppc[b*NPTS + chunk*256 + d];
    __syncthreads();

    const float w0 = W1[2*d], w1 = W1[2*d + 1], bd = b1[d];
    float acc = 0.f;
    #pragma unroll 8
    for (int jj = 0; jj < 256; jj++) {
        const float4 v = S[jj];                               // broadcast
        float a = fmaf(w1, v.y, fmaf(w0, v.x, bd));
        a = fmaxf(a, 0.f);
        acc = fmaf(v.z, a, acc);
    }
    g_upart[(b*4 + chunk)*HID + d] = acc;
}

// ---------------- K4: GCN finish — coalesced warp-per-output GEMVs ----------------
__global__ void __launch_bounds__(256)
k_gcn(const float* __restrict__ W2, const float* __restrict__ b2,
      const float* __restrict__ Wfc, const float* __restrict__ bfc,
      const float* __restrict__ Wg, const float* __restrict__ bgv) {
    const int b = blockIdx.x;
    const int tid = threadIdx.x;
    const int lane = tid & 31, w = tid >> 5;

    __shared__ float sm[HID], sz[HID];

    const float u = g_upart[(b*4 + 0)*HID + tid]
                  + g_upart[(b*4 + 1)*HID + tid]
                  + g_upart[(b*4 + 2)*HID + tid]
                  + g_upart[(b*4 + 3)*HID + tid];
    sm[tid] = u * (1.0f/1024.0f);

    if (tid < OUTD) {
        const float gl0 = g_glo[b*2], gl1 = g_glo[b*2 + 1];
        const float ge = fmaf(Wg[2*tid], gl0, fmaf(Wg[2*tid + 1], gl1, bgv[tid]));
        g_feat[b*328 + 320 + tid] = fmaxf(ge, 0.f);
    }
    __syncthreads();

    const float4* m4 = (const float4*)sm;
    const float4 ma = m4[lane], mb = m4[lane + 32];

    #pragma unroll 4
    for (int oi = 0; oi < 32; oi++) {
        const int d = w*32 + oi;
        const float4* Wr = (const float4*)(W2 + (size_t)d*HID);
        const float4 a = Wr[lane], c = Wr[lane + 32];
        float p = a.x*ma.x;
        p = fmaf(a.y, ma.y, p); p = fmaf(a.z, ma.z, p); p = fmaf(a.w, ma.w, p);
        p = fmaf(c.x, mb.x, p); p = fmaf(c.y, mb.y, p);
        p = fmaf(c.z, mb.z, p); p = fmaf(c.w, mb.w, p);
        #pragma unroll
        for (int s = 16; s > 0; s >>= 1) p += __shfl_xor_sync(0xffffffffu, p, s);
        if (lane == 0) sz[d] = p + b2[d];
    }
    __syncthreads();

    const float4* z4 = (const float4*)sz;
    const float4 za = z4[lane], zb = z4[lane + 32];

    #pragma unroll 4
    for (int oi = 0; oi < 32; oi++) {
        const int d = w*32 + oi;
        const float4* Wr = (const float4*)(Wfc + (size_t)d*HID);
        const float4 a = Wr[lane], c = Wr[lane + 32];
        float p = a.x*za.x;
        p = fmaf(a.y, za.y, p); p = fmaf(a.z, za.z, p); p = fmaf(a.w, za.w, p);
        p = fmaf(c.x, zb.x, p); p = fmaf(c.y, zb.y, p);
        p = fmaf(c.z, zb.z, p); p = fmaf(c.w, zb.w, p);
        #pragma unroll
        for (int s = 16; s > 0; s >>= 1) p += __shfl_xor_sync(0xffffffffu, p, s);
        if (lane == 0) g_feat[b*328 + 64 + d] = p + bfc[d];
    }
}

// ---------------- K5: MLP layer-1 partials (coalesced, 4 batches/block) ----------------
// grid (7, 8): slice sl, batch-group of 4.
__global__ void __launch_bounds__(256)
k_mlp1(const float* __restrict__ x, const float* __restrict__ Wm0) {
    const int sl = blockIdx.x, b0 = blockIdx.y*4;
    const int tid = threadIdx.x;
    const int lane = tid & 31, w = tid >> 5;

    __shared__ float4 sx[4][256];                             // 16KB
    #pragma unroll
    for (int bb = 0; bb < 4; bb++) {
        const float4* xp = (const float4*)(x + (size_t)(b0 + bb)*(NPTS*FDIM) + sl*1024);
        sx[bb][tid] = xp[tid];
    }
    __syncthreads();

    const int h0 = w*8;
    float acc[8][4];
    #pragma unroll
    for (int r = 0; r < 8; r++)
        #pragma unroll
        for (int bb = 0; bb < 4; bb++) acc[r][bb] = 0.f;

    #pragma unroll
    for (int it = 0; it < 8; it++) {
        const int e = it*32 + lane;
        const float4 x0 = sx[0][e], x1 = sx[1][e], x2 = sx[2][e], x3 = sx[3][e];
        #pragma unroll
        for (int r = 0; r < 8; r++) {
            const float4 wv = ((const float4*)(Wm0 + (size_t)(h0 + r)*(NPTS*FDIM) + sl*1024))[e];
            acc[r][0] = fmaf(wv.x, x0.x, acc[r][0]); acc[r][0] = fmaf(wv.y, x0.y, acc[r][0]);
            acc[r][0] = fmaf(wv.z, x0.z, acc[r][0]); acc[r][0] = fmaf(wv.w, x0.w, acc[r][0]);
            acc[r][1] = fmaf(wv.x, x1.x, acc[r][1]); acc[r][1] = fmaf(wv.y, x1.y, acc[r][1]);
            acc[r][1] = fmaf(wv.z, x1.z, acc[r][1]); acc[r][1] = fmaf(wv.w, x1.w, acc[r][1]);
            acc[r][2] = fmaf(wv.x, x2.x, acc[r][2]); acc[r][2] = fmaf(wv.y, x2.y, acc[r][2]);
            acc[r][2] = fmaf(wv.z, x2.z, acc[r][2]); acc[r][2] = fmaf(wv.w, x2.w, acc[r][2]);
            acc[r][3] = fmaf(wv.x, x3.x, acc[r][3]); acc[r][3] = fmaf(wv.y, x3.y, acc[r][3]);
            acc[r][3] = fmaf(wv.z, x3.z, acc[r][3]); acc[r][3] = fmaf(wv.w, x3.w, acc[r][3]);
        }
    }

    #pragma unroll
    for (int r = 0; r < 8; r++)
        #pragma unroll
        for (int bb = 0; bb < 4; bb++) {
            float v = acc[r][bb];
            #pragma unroll
            for (int s = 16; s > 0; s >>= 1) v += __shfl_xor_sync(0xffffffffu, v, s);
            if (lane == 0) g_mlpPart[((b0 + bb)*7 + sl)*MLP_H + h0 + r] = v;
        }
}

// ---------------- K6: MLP finish + output projection ----------------
__global__ void __launch_bounds__(64)
k_final(const float* __restrict__ Wm1, const float* __restrict__ bm1,
        const float* __restrict__ bm0,
        const float* __restrict__ Wp, const float* __restrict__ bp,
        float* __restrict__ out) {
    const int b = blockIdx.x;
    const int tid = threadIdx.x;

    __shared__ float m0[MLP_H], m1[MLP_H];
    float a = bm0[tid];
    #pragma unroll
    for (int s = 0; s < 7; s++) a += g_mlpPart[(b*7 + s)*MLP_H + tid];
    m0[tid] = fmaxf(a, 0.f);
    __syncthreads();

    float acc = bm1[tid];
    const float* wr = Wm1 + (size_t)tid*MLP_H;
    #pragma unroll 8
    for (int e = 0; e < MLP_H; e++) acc = fmaf(wr[e], m0[e], acc);
    m1[tid] = fmaxf(acc, 0.f);
    __syncthreads();

    if (tid < OUTD) {
        float o = bp[tid];
        const float* wp = Wp + (size_t)tid*328;
        #pragma unroll 8
        for (int k = 0; k < MLP_H; k++) o = fmaf(wp[k], m1[k], o);
        const float* ft = &g_feat[b*328];
        #pragma unroll 8
        for (int k = 64; k < 328; k++) o = fmaf(wp[k], ft[k], o);
        out[b*OUTD + tid] = o;
    }
}

// ---------------- launch ----------------
extern "C" void kernel_launch(void* const* d_in, const int* in_sizes, int n_in,
                              void* d_out, int out_size) {
    (void)in_sizes; (void)n_in; (void)out_size;
    const float* x   = (const float*)d_in[0];
    const float* W1  = (const float*)d_in[1];
    const float* b1  = (const float*)d_in[2];
    const float* W2  = (const float*)d_in[3];
    const float* b2  = (const float*)d_in[4];
    const float* Wfc = (const float*)d_in[5];
    const float* bfc = (const float*)d_in[6];
    const float* Wg  = (const float*)d_in[7];
    const float* bg  = (const float*)d_in[8];
    const float* Wm0 = (const float*)d_in[9];
    const float* bm0 = (const float*)d_in[10];
    const float* Wm1 = (const float*)d_in[11];
    const float* bm1 = (const float*)d_in[12];
    const float* Wp  = (const float*)d_in[13];
    const float* bp  = (const float*)d_in[14];
    float* out = (float*)d_out;

    // smallest C with sqrtf(C) >= 0.3f  =>  (d2 < C) <=> (sqrtf(d2) < 0.3f)
    float C = 0.09f;
    while (sqrtf(C) >= 0.3f) C = nextafterf(C, 0.0f);
    while (sqrtf(C) <  0.3f) C = nextafterf(C, 1.0f);

    k_adj  <<<dim3(8, BATCH), 256>>>(x, C);
    k_mlp1 <<<dim3(7, 8), 256>>>(x, Wm0);
    k_gup  <<<BATCH, 1024>>>(x);
    k_upart<<<dim3(4, BATCH), 256>>>(W1, b1);
    k_gcn  <<<BATCH, 256>>>(W2, b2, Wfc, bfc, Wg, bg);
    k_final<<<BATCH, 64>>>(Wm1, bm1, bm0, Wp, bp, out);
}

// round 3
// speedup vs baseline: 1.7425x; 1.1500x over previous
#include <cuda_runtime.h>
#include <cuda_bf16.h>
#include <cmath>

#define BATCH 32
#define NPTS  1024
#define FDIM  7
#define HID   256
#define MLP_H 64
#define OUTD  8

// ---------------- scratch (device globals) ----------------
// adjacency words: word(row k, colblock jb) at [(b*32 + jb)*1024 + k]
__device__ unsigned g_adjw[BATCH*32*NPTS];        // 4 MB
__device__ float4   g_ppc[BATCH*NPTS];            // (pp0, pp1, cc, 0)
__device__ float    g_maxpart[BATCH*4];
__device__ float    g_glo[BATCH*2];               // avg_speed, density
__device__ float    g_upart[BATCH*8*HID];
__device__ float    g_feat[BATCH*328];            // [64:320) gcn, [320:328) glo
__device__ float    g_mlpPart[BATCH*7*MLP_H];

// ---------------- KA: fused pairwise-adjacency + MLP layer-1 partials ----------------
// blocks [0,128): adjacency, b = bx>>2, j-group grp = bx&3 (256 j-rows each, all k).
// blocks [128,184): mlp1, 56 blocks = 7 slices x 8 batch-groups.
__global__ void __launch_bounds__(512)
kA(const float* __restrict__ x, const float* __restrict__ Wm0, float C) {
    const int tid = threadIdx.x;
    const int lane = tid & 31, w = tid >> 5;      // 16 warps
    __shared__ float4 S4[NPTS];                   // 16KB, shared by both roles
    __shared__ float wmax[16];

    const int bx = blockIdx.x;
    if (bx < 128) {
        // ---------------- adjacency ----------------
        const int b = bx >> 2, grp = bx & 3;
        for (int i = tid; i < NPTS; i += 512) {
            const float* xp = x + (size_t)(b*NPTS + i)*FDIM;
            const float p0 = xp[1], p1 = xp[2];
            S4[i] = make_float4(p0, p1, fmaf(p0, p0, p1*p1), 0.f);
        }
        __syncthreads();

        const int jb = grp*8 + (w & 7);           // 8 j-blocks per grid-group
        const int j  = jb*32 + lane;
        const float4 pj = S4[j];
        const float m2p0 = -2.0f*pj.x, m2p1 = -2.0f*pj.y;
        const float cj = C - pj.z;
        float emax = -1e30f;

        const int kq = (w >> 3) * 512;            // k-half per warp
        unsigned* __restrict__ outp = &g_adjw[((size_t)b*32 + jb)*NPTS];

        for (int kb = 0; kb < 16; kb++) {
            const float4* Pk = &S4[kq + kb*32];
            unsigned myw = 0;
            #pragma unroll 4
            for (int t = 0; t < 32; t++) {
                const float4 pk = Pk[t];                       // broadcast LDS.128
                const float e = fmaf(m2p0, pk.x, fmaf(m2p1, pk.y, pk.z));
                emax = fmaxf(emax, e);
                const unsigned bal = __ballot_sync(0xffffffffu, e < cj);
                if (lane == t) myw = bal;
            }
            outp[kq + kb*32 + lane] = myw;                     // coalesced
        }

        float dmax = emax + pj.z;
        #pragma unroll
        for (int s = 16; s > 0; s >>= 1)
            dmax = fmaxf(dmax, __shfl_xor_sync(0xffffffffu, dmax, s));
        if (lane == 0) wmax[w] = dmax;
        __syncthreads();
        if (tid == 0) {
            float mx = wmax[0];
            #pragma unroll
            for (int i = 1; i < 16; i++) mx = fmaxf(mx, wmax[i]);
            g_maxpart[b*4 + grp] = mx;
        }
    } else {
        // ---------------- mlp1 partials ----------------
        const int mi = bx - 128;
        const int sl = mi % 7, b0 = (mi / 7)*4;
        float4 (*sx)[256] = reinterpret_cast<float4(*)[256]>(S4);
        for (int q = tid; q < 1024; q += 512) {
            const int bb = q >> 8, e = q & 255;
            sx[bb][e] = ((const float4*)(x + (size_t)(b0 + bb)*(NPTS*FDIM) + sl*1024))[e];
        }
        __syncthreads();

        const int h0 = w*4;                        // 16 warps x 4 outputs = 64
        float acc[4][4];
        #pragma unroll
        for (int r = 0; r < 4; r++)
            #pragma unroll
            for (int bb = 0; bb < 4; bb++) acc[r][bb] = 0.f;

        #pragma unroll
        for (int it = 0; it < 8; it++) {
            const int e = it*32 + lane;
            const float4 x0 = sx[0][e], x1 = sx[1][e], x2 = sx[2][e], x3 = sx[3][e];
            #pragma unroll
            for (int r = 0; r < 4; r++) {
                const float4 wv = ((const float4*)(Wm0 + (size_t)(h0 + r)*(NPTS*FDIM) + sl*1024))[e];
                acc[r][0] = fmaf(wv.x, x0.x, acc[r][0]); acc[r][0] = fmaf(wv.y, x0.y, acc[r][0]);
                acc[r][0] = fmaf(wv.z, x0.z, acc[r][0]); acc[r][0] = fmaf(wv.w, x0.w, acc[r][0]);
                acc[r][1] = fmaf(wv.x, x1.x, acc[r][1]); acc[r][1] = fmaf(wv.y, x1.y, acc[r][1]);
                acc[r][1] = fmaf(wv.z, x1.z, acc[r][1]); acc[r][1] = fmaf(wv.w, x1.w, acc[r][1]);
                acc[r][2] = fmaf(wv.x, x2.x, acc[r][2]); acc[r][2] = fmaf(wv.y, x2.y, acc[r][2]);
                acc[r][2] = fmaf(wv.z, x2.z, acc[r][2]); acc[r][2] = fmaf(wv.w, x2.w, acc[r][2]);
                acc[r][3] = fmaf(wv.x, x3.x, acc[r][3]); acc[r][3] = fmaf(wv.y, x3.y, acc[r][3]);
                acc[r][3] = fmaf(wv.z, x3.z, acc[r][3]); acc[r][3] = fmaf(wv.w, x3.w, acc[r][3]);
            }
        }
        #pragma unroll
        for (int r = 0; r < 4; r++)
            #pragma unroll
            for (int bb = 0; bb < 4; bb++) {
                float v = acc[r][bb];
                #pragma unroll
                for (int s = 16; s > 0; s >>= 1) v += __shfl_xor_sync(0xffffffffu, v, s);
                if (lane == 0) g_mlpPart[((b0 + bb)*7 + sl)*MLP_H + h0 + r] = v;
            }
    }
}

// ---------------- KB: degrees + sparse gather + global scalars ----------------
__global__ void __launch_bounds__(1024)
k_gup(const float* __restrict__ x) {
    const int b = blockIdx.x;
    const int j = threadIdx.x;
    const int lane = j & 31, wid = j >> 5;

    __shared__ float sp0[NPTS], sp1[NPTS], sdv[NPTS];
    __shared__ float red[32];

    const float* xp = x + (size_t)(b*NPTS + j)*FDIM;
    const float p0 = xp[1], p1 = xp[2];
    const float x3 = xp[3], x4 = xp[4];
    sp0[j] = p0; sp1[j] = p1;
    float sp = sqrtf(fmaf(x3, x3, x4*x4));

    unsigned wr[32]; int cnt = 0;
    #pragma unroll
    for (int cb = 0; cb < 32; cb++) {
        wr[cb] = g_adjw[((size_t)b*32 + cb)*NPTS + j];
        cnt += __popc(wr[cb]);
    }
    const float dinv = 1.0f / sqrtf((float)cnt);
    sdv[j] = dinv;

    #pragma unroll
    for (int s = 16; s > 0; s >>= 1) sp += __shfl_xor_sync(0xffffffffu, sp, s);
    if (lane == 0) red[wid] = sp;
    __syncthreads();

    float s0 = 0.f, s1 = 0.f, t = 0.f;
    for (int cb = 0; cb < 32; cb++) {
        unsigned m = wr[cb];
        const int base = cb*32;
        while (m) {
            const int i = __ffs(m) - 1;
            m &= m - 1;
            const int k = base + i;
            const float d = sdv[k];
            s0 = fmaf(d, sp0[k], s0);
            s1 = fmaf(d, sp1[k], s1);
            t += d;
        }
    }
    g_ppc[b*NPTS + j] = make_float4(dinv*s0, dinv*s1, dinv*t, 0.f);

    if (wid == 0) {
        float v = red[lane];
        #pragma unroll
        for (int s = 16; s > 0; s >>= 1) v += __shfl_xor_sync(0xffffffffu, v, s);
        if (lane == 0) {
            float mx = fmaxf(fmaxf(g_maxpart[b*4+0], g_maxpart[b*4+1]),
                             fmaxf(g_maxpart[b*4+2], g_maxpart[b*4+3]));
            g_glo[b*2 + 0] = v * (1.0f/1024.0f);
            g_glo[b*2 + 1] = 1.0f / sqrtf(mx);
        }
    }
}

// ---------------- KC: u partials — 128-chunks, 4 independent streams ----------------
__global__ void __launch_bounds__(256)
k_upart(const float* __restrict__ W1, const float* __restrict__ b1) {
    const int chunk = blockIdx.x, b = blockIdx.y;   // 8 chunks x 32 batches
    const int d = threadIdx.x;

    __shared__ float4 S[128];
    if (d < 128) S[d] = g_ppc[b*NPTS + chunk*128 + d];
    __syncthreads();

    const float w0 = W1[2*d], w1 = W1[2*d + 1], bd = b1[d];
    float a0 = 0.f, a1 = 0.f, a2 = 0.f, a3 = 0.f;
    #pragma unroll 8
    for (int i = 0; i < 32; i++) {
        const float4 v0 = S[i], v1 = S[32 + i], v2 = S[64 + i], v3 = S[96 + i];
        float t0 = fmaf(w1, v0.y, fmaf(w0, v0.x, bd)); t0 = fmaxf(t0, 0.f);
        float t1 = fmaf(w1, v1.y, fmaf(w0, v1.x, bd)); t1 = fmaxf(t1, 0.f);
        float t2 = fmaf(w1, v2.y, fmaf(w0, v2.x, bd)); t2 = fmaxf(t2, 0.f);
        float t3 = fmaf(w1, v3.y, fmaf(w0, v3.x, bd)); t3 = fmaxf(t3, 0.f);
        a0 = fmaf(v0.z, t0, a0);
        a1 = fmaf(v1.z, t1, a1);
        a2 = fmaf(v2.z, t2, a2);
        a3 = fmaf(v3.z, t3, a3);
    }
    g_upart[(b*8 + chunk)*HID + d] = (a0 + a1) + (a2 + a3);
}

// ---------------- KD: GCN finish + global + MLP finish + output ----------------
__global__ void __launch_bounds__(256)
kD(const float* __restrict__ W2, const float* __restrict__ b2,
   const float* __restrict__ Wfc, const float* __restrict__ bfc,
   const float* __restrict__ Wg, const float* __restrict__ bgv,
   const float* __restrict__ Wm1, const float* __restrict__ bm1,
   const float* __restrict__ bm0,
   const float* __restrict__ Wp, const float* __restrict__ bp,
   float* __restrict__ out) {
    const int b = blockIdx.x;
    const int tid = threadIdx.x;
    const int lane = tid & 31, w = tid >> 5;

    __shared__ float sm[HID], sz[HID], sg[HID];
    __shared__ float m0[MLP_H], m1[MLP_H];
    __shared__ float glo8[OUTD];

    float u = 0.f;
    #pragma unroll
    for (int c = 0; c < 8; c++) u += g_upart[(b*8 + c)*HID + tid];
    sm[tid] = u * (1.0f/1024.0f);

    if (tid < OUTD) {
        const float gl0 = g_glo[b*2], gl1 = g_glo[b*2 + 1];
        const float ge = fmaf(Wg[2*tid], gl0, fmaf(Wg[2*tid + 1], gl1, bgv[tid]));
        glo8[tid] = fmaxf(ge, 0.f);
    }
    if (tid < MLP_H) {
        float a = bm0[tid];
        #pragma unroll
        for (int s = 0; s < 7; s++) a += g_mlpPart[(b*7 + s)*MLP_H + tid];
        m0[tid] = fmaxf(a, 0.f);
    }
    __syncthreads();

    const float4* m4 = (const float4*)sm;
    const float4 ma = m4[lane], mb = m4[lane + 32];
    #pragma unroll 4
    for (int oi = 0; oi < 32; oi++) {
        const int d = w*32 + oi;
        const float4* Wr = (const float4*)(W2 + (size_t)d*HID);
        const float4 a = Wr[lane], c = Wr[lane + 32];
        float p = a.x*ma.x;
        p = fmaf(a.y, ma.y, p); p = fmaf(a.z, ma.z, p); p = fmaf(a.w, ma.w, p);
        p = fmaf(c.x, mb.x, p); p = fmaf(c.y, mb.y, p);
        p = fmaf(c.z, mb.z, p); p = fmaf(c.w, mb.w, p);
        #pragma unroll
        for (int s = 16; s > 0; s >>= 1) p += __shfl_xor_sync(0xffffffffu, p, s);
        if (lane == 0) sz[d] = p + b2[d];
    }
    // mlp layer 2 in parallel region: warp-per-output over 64 outputs handled below
    __syncthreads();

    const float4* z4 = (const float4*)sz;
    const float4 za = z4[lane], zb = z4[lane + 32];
    #pragma unroll 4
    for (int oi = 0; oi < 32; oi++) {
        const int d = w*32 + oi;
        const float4* Wr = (const float4*)(Wfc + (size_t)d*HID);
        const float4 a = Wr[lane], c = Wr[lane + 32];
        float p = a.x*za.x;
        p = fmaf(a.y, za.y, p); p = fmaf(a.z, za.z, p); p = fmaf(a.w, za.w, p);
        p = fmaf(c.x, zb.x, p); p = fmaf(c.y, zb.y, p);
        p = fmaf(c.z, zb.z, p); p = fmaf(c.w, zb.w, p);
        #pragma unroll
        for (int s = 16; s > 0; s >>= 1) p += __shfl_xor_sync(0xffffffffu, p, s);
        if (lane == 0) sg[d] = p + bfc[d];
    }

    // mlp layer 2: 8 warps x 8 outputs, lanes over 64/2 elements
    {
        const int d = w*8 + (lane >> 2);           // 8 outputs per warp... (see below)
        // simpler: 64 outputs over 256 threads: 4 threads per output
        const int od = tid >> 2, q = tid & 3;      // output od, quarter q
        float p = 0.f;
        const float* wr = Wm1 + (size_t)od*MLP_H + q*16;
        const float* mm = m0 + q*16;
        #pragma unroll
        for (int e = 0; e < 16; e++) p = fmaf(wr[e], mm[e], p);
        p += __shfl_xor_sync(0xffffffffu, p, 1);
        p += __shfl_xor_sync(0xffffffffu, p, 2);
        if (q == 0) m1[od] = fmaxf(p + bm1[od], 0.f);
        (void)d;
    }
    __syncthreads();

    // output projection: 8 outputs x 32 lanes (warp 0 only)
    if (w == 0) {
        #pragma unroll
        for (int od = 0; od < OUTD; od++) {
            const float* wp = Wp + (size_t)od*(MLP_H + HID + OUTD);
            float p = 0.f;
            // k in [0,64): m1
            {
                const float v = (lane < 32) ? 0.f : 0.f;
                (void)v;
            }
            p = fmaf(wp[lane],        m1[lane],        p);
            p = fmaf(wp[32 + lane],   m1[32 + lane],   p);
            // k in [64,320): gcn (sg), 256 elems
            #pragma unroll
            for (int c = 0; c < 8; c++)
                p = fmaf(wp[64 + c*32 + lane], sg[c*32 + lane], p);
            // k in [320,328): glo
            if (lane < OUTD) p = fmaf(wp[320 + lane], glo8[lane], p);
            #pragma unroll
            for (int s = 16; s > 0; s >>= 1) p += __shfl_xor_sync(0xffffffffu, p, s);
            if (lane == 0) out[b*OUTD + od] = p + bp[od];
        }
    }
}

// ---------------- launch ----------------
extern "C" void kernel_launch(void* const* d_in, const int* in_sizes, int n_in,
                              void* d_out, int out_size) {
    (void)in_sizes; (void)n_in; (void)out_size;
    const float* x   = (const float*)d_in[0];
    const float* W1  = (const float*)d_in[1];
    const float* b1  = (const float*)d_in[2];
    const float* W2  = (const float*)d_in[3];
    const float* b2  = (const float*)d_in[4];
    const float* Wfc = (const float*)d_in[5];
    const float* bfc = (const float*)d_in[6];
    const float* Wg  = (const float*)d_in[7];
    const float* bg  = (const float*)d_in[8];
    const float* Wm0 = (const float*)d_in[9];
    const float* bm0 = (const float*)d_in[10];
    const float* Wm1 = (const float*)d_in[11];
    const float* bm1 = (const float*)d_in[12];
    const float* Wp  = (const float*)d_in[13];
    const float* bp  = (const float*)d_in[14];
    float* out = (float*)d_out;

    // smallest C with sqrtf(C) >= 0.3f  =>  (d2 < C) <=> (sqrtf(d2) < 0.3f)
    float C = 0.09f;
    while (sqrtf(C) >= 0.3f) C = nextafterf(C, 0.0f);
    while (sqrtf(C) <  0.3f) C = nextafterf(C, 1.0f);

    kA     <<<184, 512>>>(x, Wm0, C);
    k_gup  <<<BATCH, 1024>>>(x);
    k_upart<<<dim3(8, BATCH), 256>>>(W1, b1);
    kD     <<<BATCH, 256>>>(W2, b2, Wfc, bfc, Wg, bg, Wm1, bm1, bm0, Wp, bp, out);
}

// round 4
// speedup vs baseline: 1.8693x; 1.0727x over previous
#include <cuda_runtime.h>
#include <cuda_bf16.h>
#include <cmath>

#define BATCH 32
#define NPTS  1024
#define FDIM  7
#define HID   256
#define MLP_H 64
#define OUTD  8

// ---------------- scratch (device globals) ----------------
__device__ unsigned g_adjw[BATCH*32*NPTS];        // adjacency bitmask, 4 MB
__device__ float4   g_ppc[BATCH*NPTS];            // (pp0, pp1, cc, 0)
__device__ float    g_maxpart[BATCH*4];
__device__ float    g_glo[BATCH*2];               // avg_speed, density
__device__ float    g_upart[BATCH*8*HID];
__device__ float    g_mlpPart[BATCH*7*MLP_H];
__device__ float    g_E[OUTD*HID];                // folded GCN head: Wp_gcn@Wfc@W2
__device__ float    g_c0[OUTD];                   // folded GCN bias contribution

// ---------------- KA: fused adjacency + MLP layer-1 + GCN-head precompute ----------------
// blocks [0,128): adjacency (b = bx>>2, j-group = bx&3)
// blocks [128,184): mlp1 partials (56 = 7 slices x 8 batch-groups)
// blocks [184,192): GCN-head fold, one block per output row o
__global__ void __launch_bounds__(512)
kA(const float* __restrict__ x, const float* __restrict__ Wm0,
   const float* __restrict__ Wfc, const float* __restrict__ W2,
   const float* __restrict__ b2, const float* __restrict__ bfc,
   const float* __restrict__ Wp, float C) {
    const int tid = threadIdx.x;
    const int lane = tid & 31, w = tid >> 5;      // 16 warps
    __shared__ float4 S4[NPTS];                   // 16KB, role-shared
    __shared__ float wred[16];

    const int bx = blockIdx.x;
    if (bx < 128) {
        // ---------------- adjacency ----------------
        const int b = bx >> 2, grp = bx & 3;
        for (int i = tid; i < NPTS; i += 512) {
            const float* xp = x + (size_t)(b*NPTS + i)*FDIM;
            const float p0 = xp[1], p1 = xp[2];
            S4[i] = make_float4(p0, p1, fmaf(p0, p0, p1*p1), 0.f);
        }
        __syncthreads();

        const int jb = grp*8 + (w & 7);
        const int j  = jb*32 + lane;
        const float4 pj = S4[j];
        const float m2p0 = -2.0f*pj.x, m2p1 = -2.0f*pj.y;
        const float cj = C - pj.z;
        float emax = -1e30f;

        const int kq = (w >> 3) * 512;
        unsigned* __restrict__ outp = &g_adjw[((size_t)b*32 + jb)*NPTS];

        for (int kb = 0; kb < 16; kb++) {
            const float4* Pk = &S4[kq + kb*32];
            unsigned myw = 0;
            #pragma unroll 4
            for (int t = 0; t < 32; t++) {
                const float4 pk = Pk[t];                       // broadcast LDS.128
                const float e = fmaf(m2p0, pk.x, fmaf(m2p1, pk.y, pk.z));
                emax = fmaxf(emax, e);
                const unsigned bal = __ballot_sync(0xffffffffu, e < cj);
                if (lane == t) myw = bal;
            }
            outp[kq + kb*32 + lane] = myw;
        }

        float dmax = emax + pj.z;
        #pragma unroll
        for (int s = 16; s > 0; s >>= 1)
            dmax = fmaxf(dmax, __shfl_xor_sync(0xffffffffu, dmax, s));
        if (lane == 0) wred[w] = dmax;
        __syncthreads();
        if (tid == 0) {
            float mx = wred[0];
            #pragma unroll
            for (int i = 1; i < 16; i++) mx = fmaxf(mx, wred[i]);
            g_maxpart[b*4 + grp] = mx;
        }
    } else if (bx < 184) {
        // ---------------- mlp1 partials ----------------
        const int mi = bx - 128;
        const int sl = mi % 7, b0 = (mi / 7)*4;
        float4 (*sx)[256] = reinterpret_cast<float4(*)[256]>(S4);
        for (int q = tid; q < 1024; q += 512) {
            const int bb = q >> 8, e = q & 255;
            sx[bb][e] = ((const float4*)(x + (size_t)(b0 + bb)*(NPTS*FDIM) + sl*1024))[e];
        }
        __syncthreads();

        const int h0 = w*4;
        float acc[4][4];
        #pragma unroll
        for (int r = 0; r < 4; r++)
            #pragma unroll
            for (int bb = 0; bb < 4; bb++) acc[r][bb] = 0.f;

        #pragma unroll
        for (int it = 0; it < 8; it++) {
            const int e = it*32 + lane;
            const float4 x0 = sx[0][e], x1 = sx[1][e], x2 = sx[2][e], x3 = sx[3][e];
            #pragma unroll
            for (int r = 0; r < 4; r++) {
                const float4 wv = ((const float4*)(Wm0 + (size_t)(h0 + r)*(NPTS*FDIM) + sl*1024))[e];
                acc[r][0] = fmaf(wv.x, x0.x, acc[r][0]); acc[r][0] = fmaf(wv.y, x0.y, acc[r][0]);
                acc[r][0] = fmaf(wv.z, x0.z, acc[r][0]); acc[r][0] = fmaf(wv.w, x0.w, acc[r][0]);
                acc[r][1] = fmaf(wv.x, x1.x, acc[r][1]); acc[r][1] = fmaf(wv.y, x1.y, acc[r][1]);
                acc[r][1] = fmaf(wv.z, x1.z, acc[r][1]); acc[r][1] = fmaf(wv.w, x1.w, acc[r][1]);
                acc[r][2] = fmaf(wv.x, x2.x, acc[r][2]); acc[r][2] = fmaf(wv.y, x2.y, acc[r][2]);
                acc[r][2] = fmaf(wv.z, x2.z, acc[r][2]); acc[r][2] = fmaf(wv.w, x2.w, acc[r][2]);
                acc[r][3] = fmaf(wv.x, x3.x, acc[r][3]); acc[r][3] = fmaf(wv.y, x3.y, acc[r][3]);
                acc[r][3] = fmaf(wv.z, x3.z, acc[r][3]); acc[r][3] = fmaf(wv.w, x3.w, acc[r][3]);
            }
        }
        #pragma unroll
        for (int r = 0; r < 4; r++)
            #pragma unroll
            for (int bb = 0; bb < 4; bb++) {
                float v = acc[r][bb];
                #pragma unroll
                for (int s = 16; s > 0; s >>= 1) v += __shfl_xor_sync(0xffffffffu, v, s);
                if (lane == 0) g_mlpPart[((b0 + bb)*7 + sl)*MLP_H + h0 + r] = v;
            }
    } else {
        // ---------------- GCN-head fold: E[o,:] = (Wp_gcn[o,:]@Wfc)@W2 ----------------
        const int o = bx - 184;
        const float* wp = Wp + (size_t)o*(MLP_H + HID + OUTD) + MLP_H;   // Wp_gcn row o
        float* sA = (float*)S4;                                          // 256 floats

        if (tid < HID) {
            float a = 0.f;
            #pragma unroll 8
            for (int k = 0; k < HID; k++)
                a = fmaf(wp[k], Wfc[(size_t)k*HID + tid], a);            // coalesced across tid
            sA[tid] = a;
        }
        __syncthreads();

        // c0[o] = A[o,:]@b2 + Wp_gcn[o,:]@bfc
        float v = (tid < HID) ? fmaf(sA[tid], b2[tid], wp[tid]*bfc[tid]) : 0.f;
        #pragma unroll
        for (int s = 16; s > 0; s >>= 1) v += __shfl_xor_sync(0xffffffffu, v, s);
        if (lane == 0) wred[w] = v;
        __syncthreads();
        if (tid == 0) {
            float c = 0.f;
            #pragma unroll
            for (int i = 0; i < 8; i++) c += wred[i];
            g_c0[o] = c;
        }

        if (tid < HID) {
            float e = 0.f;
            #pragma unroll 8
            for (int k = 0; k < HID; k++)
                e = fmaf(sA[k], W2[(size_t)k*HID + tid], e);             // coalesced across tid
            g_E[o*HID + tid] = e;
        }
    }
}

// ---------------- KB: degrees + sparse gather + global scalars ----------------
__global__ void __launch_bounds__(1024)
k_gup(const float* __restrict__ x) {
    const int b = blockIdx.x;
    const int j = threadIdx.x;
    const int lane = j & 31, wid = j >> 5;

    __shared__ float sp0[NPTS], sp1[NPTS], sdv[NPTS];
    __shared__ float red[32];

    const float* xp = x + (size_t)(b*NPTS + j)*FDIM;
    const float p0 = xp[1], p1 = xp[2];
    const float x3 = xp[3], x4 = xp[4];
    sp0[j] = p0; sp1[j] = p1;
    float sp = sqrtf(fmaf(x3, x3, x4*x4));

    unsigned wr[32]; int cnt = 0;
    #pragma unroll
    for (int cb = 0; cb < 32; cb++) {
        wr[cb] = g_adjw[((size_t)b*32 + cb)*NPTS + j];
        cnt += __popc(wr[cb]);
    }
    const float dinv = 1.0f / sqrtf((float)cnt);
    sdv[j] = dinv;

    #pragma unroll
    for (int s = 16; s > 0; s >>= 1) sp += __shfl_xor_sync(0xffffffffu, sp, s);
    if (lane == 0) red[wid] = sp;
    __syncthreads();

    float s0 = 0.f, s1 = 0.f, t = 0.f;
    for (int cb = 0; cb < 32; cb++) {
        unsigned m = wr[cb];
        const int base = cb*32;
        while (m) {
            const int i = __ffs(m) - 1;
            m &= m - 1;
            const int k = base + i;
            const float d = sdv[k];
            s0 = fmaf(d, sp0[k], s0);
            s1 = fmaf(d, sp1[k], s1);
            t += d;
        }
    }
    g_ppc[b*NPTS + j] = make_float4(dinv*s0, dinv*s1, dinv*t, 0.f);

    if (wid == 0) {
        float v = red[lane];
        #pragma unroll
        for (int s = 16; s > 0; s >>= 1) v += __shfl_xor_sync(0xffffffffu, v, s);
        if (lane == 0) {
            float mx = fmaxf(fmaxf(g_maxpart[b*4+0], g_maxpart[b*4+1]),
                             fmaxf(g_maxpart[b*4+2], g_maxpart[b*4+3]));
            g_glo[b*2 + 0] = v * (1.0f/1024.0f);
            g_glo[b*2 + 1] = 1.0f / sqrtf(mx);
        }
    }
}

// ---------------- KC: u partials — 128-chunks, 4 independent streams ----------------
__global__ void __launch_bounds__(256)
k_upart(const float* __restrict__ W1, const float* __restrict__ b1) {
    const int chunk = blockIdx.x, b = blockIdx.y;
    const int d = threadIdx.x;

    __shared__ float4 S[128];
    if (d < 128) S[d] = g_ppc[b*NPTS + chunk*128 + d];
    __syncthreads();

    const float w0 = W1[2*d], w1 = W1[2*d + 1], bd = b1[d];
    float a0 = 0.f, a1 = 0.f, a2 = 0.f, a3 = 0.f;
    #pragma unroll 8
    for (int i = 0; i < 32; i++) {
        const float4 v0 = S[i], v1 = S[32 + i], v2 = S[64 + i], v3 = S[96 + i];
        float t0 = fmaf(w1, v0.y, fmaf(w0, v0.x, bd)); t0 = fmaxf(t0, 0.f);
        float t1 = fmaf(w1, v1.y, fmaf(w0, v1.x, bd)); t1 = fmaxf(t1, 0.f);
        float t2 = fmaf(w1, v2.y, fmaf(w0, v2.x, bd)); t2 = fmaxf(t2, 0.f);
        float t3 = fmaf(w1, v3.y, fmaf(w0, v3.x, bd)); t3 = fmaxf(t3, 0.f);
        a0 = fmaf(v0.z, t0, a0);
        a1 = fmaf(v1.z, t1, a1);
        a2 = fmaf(v2.z, t2, a2);
        a3 = fmaf(v3.z, t3, a3);
    }
    g_upart[(b*8 + chunk)*HID + d] = (a0 + a1) + (a2 + a3);
}

// ---------------- KD: folded head — m, mlp finish, glo, output ----------------
__global__ void __launch_bounds__(256)
kD(const float* __restrict__ Wg, const float* __restrict__ bgv,
   const float* __restrict__ Wm1, const float* __restrict__ bm1,
   const float* __restrict__ bm0,
   const float* __restrict__ Wp, const float* __restrict__ bp,
   float* __restrict__ out) {
    const int b = blockIdx.x;
    const int tid = threadIdx.x;
    const int lane = tid & 31, w = tid >> 5;

    __shared__ float sm[HID];
    __shared__ float m0[MLP_H], m1[MLP_H];
    __shared__ float glo8[OUTD];

    float u = 0.f;
    #pragma unroll
    for (int c = 0; c < 8; c++) u += g_upart[(b*8 + c)*HID + tid];
    sm[tid] = u * (1.0f/1024.0f);

    if (tid < OUTD) {
        const float gl0 = g_glo[b*2], gl1 = g_glo[b*2 + 1];
        const float ge = fmaf(Wg[2*tid], gl0, fmaf(Wg[2*tid + 1], gl1, bgv[tid]));
        glo8[tid] = fmaxf(ge, 0.f);
    }
    if (tid < MLP_H) {
        float a = bm0[tid];
        #pragma unroll
        for (int s = 0; s < 7; s++) a += g_mlpPart[(b*7 + s)*MLP_H + tid];
        m0[tid] = fmaxf(a, 0.f);
    }
    __syncthreads();

    // mlp layer 2: 64 outputs x 4 threads
    {
        const int od = tid >> 2, q = tid & 3;
        const float4* wr4 = (const float4*)(Wm1 + (size_t)od*MLP_H + q*16);
        const float4* mm4 = (const float4*)(m0 + q*16);
        float p = 0.f;
        #pragma unroll
        for (int e = 0; e < 4; e++) {
            const float4 wv = wr4[e], mv = mm4[e];
            p = fmaf(wv.x, mv.x, p); p = fmaf(wv.y, mv.y, p);
            p = fmaf(wv.z, mv.z, p); p = fmaf(wv.w, mv.w, p);
        }
        p += __shfl_xor_sync(0xffffffffu, p, 1);
        p += __shfl_xor_sync(0xffffffffu, p, 2);
        if (q == 0) m1[od] = fmaxf(p + bm1[od], 0.f);
    }
    __syncthreads();

    // output: warp o computes out[b, o]
    {
        const int o = w;     // 8 warps, 8 outputs
        const float* Eo = g_E + o*HID;
        const float* wp = Wp + (size_t)o*(MLP_H + HID + OUTD);
        float p = 0.f;
        #pragma unroll
        for (int c = 0; c < 8; c++)
            p = fmaf(Eo[c*32 + lane], sm[c*32 + lane], p);
        p = fmaf(wp[lane],      m1[lane],      p);
        p = fmaf(wp[32 + lane], m1[32 + lane], p);
        if (lane < OUTD) p = fmaf(wp[320 + lane], glo8[lane], p);
        #pragma unroll
        for (int s = 16; s > 0; s >>= 1) p += __shfl_xor_sync(0xffffffffu, p, s);
        if (lane == 0) out[b*OUTD + o] = p + bp[o] + g_c0[o];
    }
}

// ---------------- launch ----------------
extern "C" void kernel_launch(void* const* d_in, const int* in_sizes, int n_in,
                              void* d_out, int out_size) {
    (void)in_sizes; (void)n_in; (void)out_size;
    const float* x   = (const float*)d_in[0];
    const float* W1  = (const float*)d_in[1];
    const float* b1  = (const float*)d_in[2];
    const float* W2  = (const float*)d_in[3];
    const float* b2  = (const float*)d_in[4];
    const float* Wfc = (const float*)d_in[5];
    const float* bfc = (const float*)d_in[6];
    const float* Wg  = (const float*)d_in[7];
    const float* bg  = (const float*)d_in[8];
    const float* Wm0 = (const float*)d_in[9];
    const float* bm0 = (const float*)d_in[10];
    const float* Wm1 = (const float*)d_in[11];
    const float* bm1 = (const float*)d_in[12];
    const float* Wp  = (const float*)d_in[13];
    const float* bp  = (const float*)d_in[14];
    float* out = (float*)d_out;

    // smallest C with sqrtf(C) >= 0.3f  =>  (d2 < C) <=> (sqrtf(d2) < 0.3f)
    float C = 0.09f;
    while (sqrtf(C) >= 0.3f) C = nextafterf(C, 0.0f);
    while (sqrtf(C) <  0.3f) C = nextafterf(C, 1.0f);

    kA     <<<192, 512>>>(x, Wm0, Wfc, W2, b2, bfc, Wp, C);
    k_gup  <<<BATCH, 1024>>>(x);
    k_upart<<<dim3(8, BATCH), 256>>>(W1, b1);
    kD     <<<BATCH, 256>>>(Wg, bg, Wm1, bm1, bm0, Wp, bp, out);
}